// round 1
// baseline (speedup 1.0000x reference)
#include <cuda_runtime.h>
#include <math_constants.h>
#include <limits.h>

#define NPTS 500000
#define BGR 64
#define DIN 64
#define DH 128
#define DO 128

// ---------------- device scratch (no allocations allowed) ----------------
__device__ float g_psum[BGR][3];
__device__ float g_cnt[BGR];
__device__ unsigned long long g_amin[BGR];
__device__ float g_cc[BGR][DH];   // per-graph folded bias c_g

__device__ __forceinline__ void atomicMaxFloat(float* addr, float val) {
    if (val >= 0.0f) atomicMax((int*)addr, __float_as_int(val));
    else             atomicMin((unsigned int*)addr, __float_as_uint(val));
}

// ---------------- init: zero scratch, set out[0..8192) = -inf ----------------
__global__ void k_init(float* out, int out_size) {
    int i = blockIdx.x * blockDim.x + threadIdx.x;
    if (blockIdx.x == 0) {
        if (threadIdx.x < BGR) { g_cnt[threadIdx.x] = 0.f; g_amin[threadIdx.x] = ~0ull; }
        if (threadIdx.x < BGR * 3) ((float*)g_psum)[threadIdx.x] = 0.f;
    }
    int lim = (BGR * DO < out_size) ? BGR * DO : out_size;
    for (int j = i; j < lim; j += gridDim.x * blockDim.x) out[j] = -CUDART_INF_F;
}

// ---------------- per-graph pos sums + counts (chunked, few atomics) -------
__global__ void k_stats(const float* __restrict__ pos, const int* __restrict__ batch) {
    const int T = gridDim.x * blockDim.x;
    int t = blockIdx.x * blockDim.x + threadIdx.x;
    int chunk = (NPTS + T - 1) / T;
    int s = t * chunk;
    int e = s + chunk; if (e > NPTS) e = NPTS;
    if (s >= e) return;
    int cg = batch[s];
    float sx = 0.f, sy = 0.f, sz = 0.f, c = 0.f;
    for (int i = s; i < e; i++) {
        int g = batch[i];
        if (g != cg) {
            atomicAdd(&g_psum[cg][0], sx); atomicAdd(&g_psum[cg][1], sy);
            atomicAdd(&g_psum[cg][2], sz); atomicAdd(&g_cnt[cg], c);
            cg = g; sx = sy = sz = 0.f; c = 0.f;
        }
        sx += pos[3 * i]; sy += pos[3 * i + 1]; sz += pos[3 * i + 2]; c += 1.f;
    }
    atomicAdd(&g_psum[cg][0], sx); atomicAdd(&g_psum[cg][1], sy);
    atomicAdd(&g_psum[cg][2], sz); atomicAdd(&g_cnt[cg], c);
}

// ---------------- per-graph argmin of dist to COM (packed 64-bit min) ------
__global__ void k_argmin(const float* __restrict__ pos, const int* __restrict__ batch) {
    const int T = gridDim.x * blockDim.x;
    int t = blockIdx.x * blockDim.x + threadIdx.x;
    int chunk = (NPTS + T - 1) / T;
    int s = t * chunk;
    int e = s + chunk; if (e > NPTS) e = NPTS;
    if (s >= e) return;
    int cg = -1;
    float cx = 0.f, cy = 0.f, cz = 0.f;
    unsigned long long best = ~0ull;
    for (int i = s; i < e; i++) {
        int g = batch[i];
        if (g != cg) {
            if (cg >= 0) atomicMin(&g_amin[cg], best);
            cg = g; best = ~0ull;
            float cnt = fmaxf(g_cnt[g], 1.0f);
            cx = g_psum[g][0] / cnt; cy = g_psum[g][1] / cnt; cz = g_psum[g][2] / cnt;
        }
        float dx = pos[3 * i] - cx, dy = pos[3 * i + 1] - cy, dz = pos[3 * i + 2] - cz;
        float d = sqrtf(dx * dx + dy * dy + dz * dz);
        unsigned long long key = ((unsigned long long)__float_as_uint(d) << 32) | (unsigned)i;
        if (key < best) best = key;
    }
    if (cg >= 0) atomicMin(&g_amin[cg], best);
}

// ---------------- fold x_dst/pos_dst into per-graph bias; emit small outputs
__global__ void k_center(const float* __restrict__ x, const float* __restrict__ pos,
                         const int* __restrict__ batch, const float* __restrict__ lf,
                         const float* __restrict__ W1, const float* __restrict__ b1,
                         float* out, int out_size) {
    int g = blockIdx.x;
    int j = threadIdx.x;  // 0..127
    unsigned long long key = g_amin[g];
    int idx = (g_cnt[g] > 0.f) ? (int)(unsigned)(key & 0xffffffffu) : (NPTS - 1);
    const float* xr = x + (long long)idx * DIN;
    const float* pr = pos + (long long)idx * 3;
    float c = b1[j];
    #pragma unroll 8
    for (int k = 0; k < DIN; k++)
        c += xr[k] * (W1[k * DH + j] - W1[(DIN + k) * DH + j]);
    #pragma unroll
    for (int m = 0; m < 3; m++)
        c -= pr[m] * W1[(2 * DIN + m) * DH + j];
    g_cc[g][j] = c;
    // outputs: pos_dst, batch[idx], lframes_dst  (after the [B,128] maxes)
    if (j < 3) { int o = BGR * DO + g * 3 + j;            if (o < out_size) out[o] = pr[j]; }
    if (j == 0){ int o = BGR * DO + BGR * 3 + g;          if (o < out_size) out[o] = (float)batch[idx]; }
    if (j < 9) { int o = BGR * DO + BGR * 3 + BGR + g*9+j;if (o < out_size) out[o] = lf[(long long)idx * 9 + j]; }
}

// ---------------- fused MLP + segment-max main kernel ----------------------
// tile: 128 rows x 128 cols, 256 threads, 8x8 register tiles
#define RT 128
#define HP 132                    // Hs / XsT pitch (floats), multiple of 4
// smem layout (floats):
//   [0 .. 16640)        XsT(64*132=8448) + W1s(64*128=8192)   -- reused as W2s(16384) in phase 2
//   [16640 .. 33536)    Hs (128*132)
//   [33536 .. 33920)    px/py/pz (3*128)
//   [33920 .. 34304)    wps (3*128)
//   [34304 .. 34560)    cgsA(128) + cgsB(128)
//   [34560 .. 36608)    red (16*128)
//   [36608 .. 36736)    gbs (128 ints)
#define SMEM_FLOATS 36736

__global__ __launch_bounds__(256) void k_main(
    const float* __restrict__ x, const float* __restrict__ pos,
    const int* __restrict__ batch, const float* __restrict__ W1,
    const float* __restrict__ W2, const float* __restrict__ b2,
    float* __restrict__ out) {

    extern __shared__ float sm[];
    float* XsT = sm;                  // [64][HP]
    float* W1s = sm + 64 * HP;        // [64][128]
    float* W2s = sm;                  // reuse, [128][128]
    float* Hs  = sm + 16640;          // [128][HP]
    float* px  = sm + 33536;
    float* py  = px + 128;
    float* pz  = py + 128;
    float* wps = sm + 33920;          // [3][128]
    float* cgsA = sm + 34304;
    float* cgsB = cgsA + 128;
    float* red  = sm + 34560;         // [16][128]
    int*   gbs  = (int*)(sm + 36608); // [128]
    __shared__ int s_gmin, s_gmax;

    const int tid = threadIdx.x;
    const int ty = tid >> 4, tx = tid & 15;
    const int row0 = blockIdx.x * RT;

    if (tid == 0) { s_gmin = INT_MAX; s_gmax = -1; }
    __syncthreads();

    // --- load x tile transposed: XsT[k][r] = x[row0+r][k]
    for (int t = tid; t < RT * DIN / 4; t += 256) {
        int r = t >> 4, k4 = t & 15;
        int row = row0 + r;
        float4 v = make_float4(0.f, 0.f, 0.f, 0.f);
        if (row < NPTS) v = ((const float4*)x)[(long long)row * 16 + k4];
        XsT[(k4 * 4 + 0) * HP + r] = v.x;
        XsT[(k4 * 4 + 1) * HP + r] = v.y;
        XsT[(k4 * 4 + 2) * HP + r] = v.z;
        XsT[(k4 * 4 + 3) * HP + r] = v.w;
    }
    // --- W1x = W1 rows 64..127 (x coefficient)
    for (int t = tid; t < 64 * DH / 4; t += 256)
        ((float4*)W1s)[t] = ((const float4*)(W1 + DIN * DH))[t];
    // --- Wp = W1 rows 128..130
    for (int t = tid; t < 3 * DH / 4; t += 256)
        ((float4*)wps)[t] = ((const float4*)(W1 + 2 * DIN * DH))[t];
    // --- pos + batch for tile
    for (int t = tid; t < RT; t += 256) {
        int row = row0 + t;
        if (row < NPTS) {
            px[t] = pos[3 * row]; py[t] = pos[3 * row + 1]; pz[t] = pos[3 * row + 2];
            int g = batch[row];
            gbs[t] = g;
            atomicMin(&s_gmin, g);
            atomicMax(&s_gmax, g);
        } else {
            px[t] = py[t] = pz[t] = 0.f;
            gbs[t] = -1;
        }
    }
    __syncthreads();
    const int gmin = s_gmin, gmax = s_gmax;
    if (tid < 128) {
        cgsA[tid] = g_cc[gmin][tid];
        cgsB[tid] = g_cc[gmax][tid];
    }
    __syncthreads();

    // ---------- phase 1: H = relu(X@W1x + pos@Wp + c_g) ----------
    float acc[8][8];
    #pragma unroll
    for (int i = 0; i < 8; i++)
        #pragma unroll
        for (int j = 0; j < 8; j++) acc[i][j] = 0.f;

    #pragma unroll 8
    for (int k = 0; k < DIN; k++) {
        float4 a0 = *(const float4*)(XsT + k * HP + ty * 8);
        float4 a1 = *(const float4*)(XsT + k * HP + ty * 8 + 4);
        float4 b0 = *(const float4*)(W1s + k * DH + tx * 8);
        float4 b1v = *(const float4*)(W1s + k * DH + tx * 8 + 4);
        float a[8] = {a0.x, a0.y, a0.z, a0.w, a1.x, a1.y, a1.z, a1.w};
        float b[8] = {b0.x, b0.y, b0.z, b0.w, b1v.x, b1v.y, b1v.z, b1v.w};
        #pragma unroll
        for (int i = 0; i < 8; i++)
            #pragma unroll
            for (int j = 0; j < 8; j++) acc[i][j] = fmaf(a[i], b[j], acc[i][j]);
    }

    // epilogue: add pos term + per-graph bias, relu, store to Hs row-major
    #pragma unroll
    for (int i = 0; i < 8; i++) {
        int rl = ty * 8 + i;
        int g = gbs[rl];
        const float* cg = (g == gmin) ? cgsA : ((g == gmax) ? cgsB : (g >= 0 ? &g_cc[g][0] : cgsA));
        float ppx = px[rl], ppy = py[rl], ppz = pz[rl];
        float v[8];
        #pragma unroll
        for (int j = 0; j < 8; j++) {
            int c = tx * 8 + j;
            float t = acc[i][j] + ppx * wps[c] + ppy * wps[128 + c] + ppz * wps[256 + c] + cg[c];
            t = fmaxf(t, 0.f);
            v[j] = (g < 0) ? 0.f : t;
        }
        *(float4*)(Hs + rl * HP + tx * 8)     = make_float4(v[0], v[1], v[2], v[3]);
        *(float4*)(Hs + rl * HP + tx * 8 + 4) = make_float4(v[4], v[5], v[6], v[7]);
    }
    __syncthreads();

    // ---------- load W2 into the freed XsT/W1s region ----------
    for (int t = tid; t < DH * DO / 4; t += 256)
        ((float4*)W2s)[t] = ((const float4*)W2)[t];
    __syncthreads();

    // ---------- phase 2: M = H@W2 ----------
    float acc2[8][8];
    #pragma unroll
    for (int i = 0; i < 8; i++)
        #pragma unroll
        for (int j = 0; j < 8; j++) acc2[i][j] = 0.f;

    #pragma unroll 4
    for (int k = 0; k < DH; k++) {
        float a[8];
        #pragma unroll
        for (int i = 0; i < 8; i++) a[i] = Hs[(ty * 8 + i) * HP + k];
        float4 b0 = *(const float4*)(W2s + k * DO + tx * 8);
        float4 b1v = *(const float4*)(W2s + k * DO + tx * 8 + 4);
        float b[8] = {b0.x, b0.y, b0.z, b0.w, b1v.x, b1v.y, b1v.z, b1v.w};
        #pragma unroll
        for (int i = 0; i < 8; i++)
            #pragma unroll
            for (int j = 0; j < 8; j++) acc2[i][j] = fmaf(a[i], b[j], acc2[i][j]);
    }

    float b2r[8];
    #pragma unroll
    for (int j = 0; j < 8; j++) b2r[j] = b2[tx * 8 + j];

    __syncthreads();

    bool fast = (gbs[0] >= 0) && (gbs[0] == gbs[RT - 1]);  // sorted batch => uniform tile
    if (fast) {
        int g = gbs[0];
        #pragma unroll
        for (int j = 0; j < 8; j++) {
            float m = acc2[0][j];
            #pragma unroll
            for (int i = 1; i < 8; i++) m = fmaxf(m, acc2[i][j]);
            red[ty * 128 + tx * 8 + j] = m + b2r[j];
        }
        __syncthreads();
        if (tid < 128) {
            float m = red[tid];
            #pragma unroll
            for (int t = 1; t < 16; t++) m = fmaxf(m, red[t * 128 + tid]);
            atomicMaxFloat(&out[g * DO + tid], m);
        }
    } else {
        // rare: tile crosses a graph boundary or has padded rows
        #pragma unroll
        for (int j = 0; j < 8; j++) {
            int c = tx * 8 + j;
            float bb = b2r[j];
            int curg = -2; float curm = 0.f;
            #pragma unroll
            for (int i = 0; i < 8; i++) {
                int g = gbs[ty * 8 + i];
                if (g < 0) continue;
                float v = acc2[i][j] + bb;
                if (g != curg) {
                    if (curg >= 0) atomicMaxFloat(&out[curg * DO + c], curm);
                    curg = g; curm = v;
                } else {
                    curm = fmaxf(curm, v);
                }
            }
            if (curg >= 0) atomicMaxFloat(&out[curg * DO + c], curm);
        }
        __syncthreads();
    }
}

// ---------------- launch ----------------
extern "C" void kernel_launch(void* const* d_in, const int* in_sizes, int n_in,
                              void* d_out, int out_size) {
    const float* x     = (const float*)d_in[0];
    const float* pos   = (const float*)d_in[1];
    const int*   batch = (const int*)d_in[2];
    const float* lf    = (const float*)d_in[3];
    const float* W1    = (const float*)d_in[4];
    const float* b1    = (const float*)d_in[5];
    const float* W2    = (const float*)d_in[6];
    const float* b2    = (const float*)d_in[7];
    float* out = (float*)d_out;

    static bool attr_set = false;
    if (!attr_set) {
        cudaFuncSetAttribute(k_main, cudaFuncAttributeMaxDynamicSharedMemorySize,
                             SMEM_FLOATS * 4);
        attr_set = true;
    }

    k_init<<<32, 256>>>(out, out_size);
    k_stats<<<64, 256>>>(pos, batch);
    k_argmin<<<64, 256>>>(pos, batch);
    k_center<<<BGR, DH>>>(x, pos, batch, lf, W1, b1, out, out_size);
    int grid = (NPTS + RT - 1) / RT;
    k_main<<<grid, 256, SMEM_FLOATS * 4>>>(x, pos, batch, W1, W2, b2, out);
}

// round 3
// speedup vs baseline: 2.6933x; 2.6933x over previous
#include <cuda_runtime.h>
#include <cuda_bf16.h>
#include <math_constants.h>
#include <limits.h>
#include <stdint.h>

#define NPTS 500000
#define BGR 64
#define DIN 64
#define DH 128
#define DO 128
#define TILE 128

// ---------------- device scratch ----------------
__device__ float g_psum[BGR][3];
__device__ float g_cnt[BGR];
__device__ unsigned long long g_amin[BGR];
__device__ float g_cc[BGR][DH];
// weight fragments: [kchunk][ntile(16)][lane(32)] -> uint4 {bhi0,bhi1,blo0,blo1}
__device__ uint4 g_W1f[4 * 16 * 32];
__device__ uint4 g_W2f[8 * 16 * 32];

__device__ __forceinline__ void atomicMaxFloat(float* addr, float val) {
    if (val >= 0.0f) atomicMax((int*)addr, __float_as_int(val));
    else             atomicMin((unsigned int*)addr, __float_as_uint(val));
}

__device__ __forceinline__ uint32_t pk_hi(float a, float b) {
    __nv_bfloat162 t = __halves2bfloat162(__float2bfloat16_rn(a), __float2bfloat16_rn(b));
    return *(uint32_t*)&t;
}
__device__ __forceinline__ uint32_t pk_lo(float a, float b) {
    float ra = a - __bfloat162float(__float2bfloat16_rn(a));
    float rb = b - __bfloat162float(__float2bfloat16_rn(b));
    __nv_bfloat162 t = __halves2bfloat162(__float2bfloat16_rn(ra), __float2bfloat16_rn(rb));
    return *(uint32_t*)&t;
}

__device__ __forceinline__ void mma16816(float* c, const uint32_t* a, uint32_t b0, uint32_t b1) {
    asm volatile(
        "mma.sync.aligned.m16n8k16.row.col.f32.bf16.bf16.f32 "
        "{%0,%1,%2,%3}, {%4,%5,%6,%7}, {%8,%9}, {%0,%1,%2,%3};"
        : "+f"(c[0]), "+f"(c[1]), "+f"(c[2]), "+f"(c[3])
        : "r"(a[0]), "r"(a[1]), "r"(a[2]), "r"(a[3]), "r"(b0), "r"(b1));
}

// ---------------- small kernels ----------------
__global__ void k_init(float* out, int out_size) {
    int i = blockIdx.x * blockDim.x + threadIdx.x;
    if (blockIdx.x == 0) {
        if (threadIdx.x < BGR) { g_cnt[threadIdx.x] = 0.f; g_amin[threadIdx.x] = ~0ull; }
        if (threadIdx.x < BGR * 3) ((float*)g_psum)[threadIdx.x] = 0.f;
    }
    int lim = (BGR * DO < out_size) ? BGR * DO : out_size;
    for (int j = i; j < lim; j += gridDim.x * blockDim.x) out[j] = -CUDART_INF_F;
}

__global__ void k_stats(const float* __restrict__ pos, const int* __restrict__ batch) {
    const int T = gridDim.x * blockDim.x;
    int t = blockIdx.x * blockDim.x + threadIdx.x;
    int chunk = (NPTS + T - 1) / T;
    int s = t * chunk;
    int e = s + chunk; if (e > NPTS) e = NPTS;
    if (s >= e) return;
    int cg = batch[s];
    float sx = 0.f, sy = 0.f, sz = 0.f, c = 0.f;
    for (int i = s; i < e; i++) {
        int g = batch[i];
        if (g != cg) {
            atomicAdd(&g_psum[cg][0], sx); atomicAdd(&g_psum[cg][1], sy);
            atomicAdd(&g_psum[cg][2], sz); atomicAdd(&g_cnt[cg], c);
            cg = g; sx = sy = sz = 0.f; c = 0.f;
        }
        sx += pos[3 * i]; sy += pos[3 * i + 1]; sz += pos[3 * i + 2]; c += 1.f;
    }
    atomicAdd(&g_psum[cg][0], sx); atomicAdd(&g_psum[cg][1], sy);
    atomicAdd(&g_psum[cg][2], sz); atomicAdd(&g_cnt[cg], c);
}

__global__ void k_argmin(const float* __restrict__ pos, const int* __restrict__ batch) {
    const int T = gridDim.x * blockDim.x;
    int t = blockIdx.x * blockDim.x + threadIdx.x;
    int chunk = (NPTS + T - 1) / T;
    int s = t * chunk;
    int e = s + chunk; if (e > NPTS) e = NPTS;
    if (s >= e) return;
    int cg = -1;
    float cx = 0.f, cy = 0.f, cz = 0.f;
    unsigned long long best = ~0ull;
    for (int i = s; i < e; i++) {
        int g = batch[i];
        if (g != cg) {
            if (cg >= 0) atomicMin(&g_amin[cg], best);
            cg = g; best = ~0ull;
            float cnt = fmaxf(g_cnt[g], 1.0f);
            cx = g_psum[g][0] / cnt; cy = g_psum[g][1] / cnt; cz = g_psum[g][2] / cnt;
        }
        float dx = pos[3 * i] - cx, dy = pos[3 * i + 1] - cy, dz = pos[3 * i + 2] - cz;
        float d = sqrtf(dx * dx + dy * dy + dz * dz);
        unsigned long long key = ((unsigned long long)__float_as_uint(d) << 32) | (unsigned)i;
        if (key < best) best = key;
    }
    if (cg >= 0) atomicMin(&g_amin[cg], best);
}

__global__ void k_center(const float* __restrict__ x, const float* __restrict__ pos,
                         const int* __restrict__ batch, const float* __restrict__ lf,
                         const float* __restrict__ W1, const float* __restrict__ b1,
                         float* out, int out_size) {
    __shared__ float sx[DIN];
    __shared__ float sp[3];
    __shared__ int sidx;
    int g = blockIdx.x;
    int j = threadIdx.x;  // 0..127
    if (j == 0) {
        unsigned long long key = g_amin[g];
        sidx = (g_cnt[g] > 0.f) ? (int)(unsigned)(key & 0xffffffffu) : (NPTS - 1);
    }
    __syncthreads();
    int idx = sidx;
    if (j < DIN) sx[j] = x[(size_t)idx * DIN + j];
    if (j < 3) sp[j] = pos[3 * idx + j];
    __syncthreads();
    float c = b1[j];
    #pragma unroll 8
    for (int k = 0; k < DIN; k++)
        c += sx[k] * (W1[k * DH + j] - W1[(DIN + k) * DH + j]);
    c -= sp[0] * W1[(2 * DIN) * DH + j] + sp[1] * W1[(2 * DIN + 1) * DH + j]
       + sp[2] * W1[(2 * DIN + 2) * DH + j];
    g_cc[g][j] = c;
    if (j < 3)  { int o = BGR * DO + g * 3 + j;               if (o < out_size) out[o] = sp[j]; }
    if (j == 0) { int o = BGR * DO + BGR * 3 + g;             if (o < out_size) out[o] = (float)batch[idx]; }
    if (j < 9)  { int o = BGR * DO + BGR * 3 + BGR + g*9 + j; if (o < out_size) out[o] = lf[(size_t)idx * 9 + j]; }
}

// ---------------- weight prep: pack mma.sync B-fragments, hi/lo split ------
__global__ void k_wprep(const float* __restrict__ W1, const float* __restrict__ W2) {
    int i = blockIdx.x * blockDim.x + threadIdx.x;
    if (i < 4 * 16 * 32) {   // W1x fragment: t(4), j(16), l(32)
        int l = i & 31, t = i >> 9;
        int n = 8 * ((i >> 5) & 15) + (l >> 2);
        int k0 = 16 * t + 2 * (l & 3);
        float w00 = W1[(DIN + k0) * DH + n];
        float w01 = W1[(DIN + k0 + 1) * DH + n];
        float w10 = W1[(DIN + k0 + 8) * DH + n];
        float w11 = W1[(DIN + k0 + 9) * DH + n];
        uint4 v;
        v.x = pk_hi(w00, w01); v.y = pk_hi(w10, w11);
        v.z = pk_lo(w00, w01); v.w = pk_lo(w10, w11);
        g_W1f[i] = v;
    }
    if (i < 8 * 16 * 32) {   // W2 fragment: t(8), j(16), l(32)
        int l = i & 31, t = i >> 9;
        int n = 8 * ((i >> 5) & 15) + (l >> 2);
        int k0 = 16 * t + 2 * (l & 3);
        float w00 = W2[k0 * DO + n];
        float w01 = W2[(k0 + 1) * DO + n];
        float w10 = W2[(k0 + 8) * DO + n];
        float w11 = W2[(k0 + 9) * DO + n];
        uint4 v;
        v.x = pk_hi(w00, w01); v.y = pk_hi(w10, w11);
        v.z = pk_lo(w00, w01); v.w = pk_lo(w10, w11);
        g_W2f[i] = v;
    }
}

// ---------------- main fused mma.sync kernel ----------------
__global__ __launch_bounds__(256) void k_main(
    const float* __restrict__ x, const float* __restrict__ pos,
    const int* __restrict__ batch, const float* __restrict__ W1,
    const float* __restrict__ b2, float* __restrict__ out) {

    __shared__ float wpx[128], wpy[128], wpz[128];
    __shared__ float cgs[128], b2s[128];
    __shared__ float px[128], py[128], pz[128];
    __shared__ float red[8 * 128];
    __shared__ int gbs[128];
    __shared__ int s_uni, s_gu;

    const int tid = threadIdx.x;
    const int wid = tid >> 5, l = tid & 31;
    const int row0 = blockIdx.x * TILE;

    // setup
    if (tid < 128) {
        wpx[tid] = W1[(2 * DIN + 0) * DH + tid];
        wpy[tid] = W1[(2 * DIN + 1) * DH + tid];
        wpz[tid] = W1[(2 * DIN + 2) * DH + tid];
        b2s[tid] = b2[tid];
        int row = row0 + tid;
        if (row < NPTS) {
            px[tid] = pos[3 * row]; py[tid] = pos[3 * row + 1]; pz[tid] = pos[3 * row + 2];
            gbs[tid] = batch[row];
        } else {
            px[tid] = py[tid] = pz[tid] = 0.f;
            gbs[tid] = -1;
        }
    }
    __syncthreads();
    const int gu = gbs[0];
    const bool uni = (gu >= 0) && (gu == gbs[127]);
    if (tid < 128) cgs[tid] = (gu >= 0) ? g_cc[gu][tid] : 0.f;
    __syncthreads();

    const int rr0 = wid * 16 + (l >> 2);
    const int rr1 = rr0 + 8;
    const int r0 = row0 + rr0, r1 = row0 + rr1;
    const int m4 = 2 * (l & 3);

    // ---------- phase 1: acc1 = X @ W1x (3-term bf16 split) ----------
    float acc1[16][4];
    #pragma unroll
    for (int j = 0; j < 16; j++)
        #pragma unroll
        for (int q = 0; q < 4; q++) acc1[j][q] = 0.f;

    #pragma unroll
    for (int t = 0; t < 4; t++) {
        const int kb = 16 * t + m4;
        float2 x00 = make_float2(0.f, 0.f), x01 = x00, x10 = x00, x11 = x00;
        if (r0 < NPTS) {
            x00 = *(const float2*)(x + (size_t)r0 * DIN + kb);
            x01 = *(const float2*)(x + (size_t)r0 * DIN + kb + 8);
        }
        if (r1 < NPTS) {
            x10 = *(const float2*)(x + (size_t)r1 * DIN + kb);
            x11 = *(const float2*)(x + (size_t)r1 * DIN + kb + 8);
        }
        uint32_t Ahi[4] = { pk_hi(x00.x, x00.y), pk_hi(x10.x, x10.y),
                            pk_hi(x01.x, x01.y), pk_hi(x11.x, x11.y) };
        uint32_t Alo[4] = { pk_lo(x00.x, x00.y), pk_lo(x10.x, x10.y),
                            pk_lo(x01.x, x01.y), pk_lo(x11.x, x11.y) };
        const uint4* wf = g_W1f + (t * 16) * 32 + l;
        #pragma unroll
        for (int j = 0; j < 16; j++) {
            uint4 B = wf[j * 32];
            mma16816(acc1[j], Ahi, B.x, B.y);   // hh
            mma16816(acc1[j], Ahi, B.z, B.w);   // hi * lo
            mma16816(acc1[j], Alo, B.x, B.y);   // lo * hi
        }
    }

    // ---------- epilogue 1: + pos*Wp + c_g, relu, split -> A-frags ----------
    const float p0x = px[rr0], p0y = py[rr0], p0z = pz[rr0];
    const float p1x = px[rr1], p1y = py[rr1], p1z = pz[rr1];
    const int g0 = gbs[rr0], g1 = gbs[rr1];

    uint32_t ahi[16][2], alo[16][2];
    #pragma unroll
    for (int j = 0; j < 16; j++) {
        int c0 = 8 * j + m4;
        float2 wx = *(float2*)&wpx[c0];
        float2 wy = *(float2*)&wpy[c0];
        float2 wz = *(float2*)&wpz[c0];
        float2 cv0, cv1;
        if (uni) {
            cv0 = *(float2*)&cgs[c0]; cv1 = cv0;
        } else {
            cv0 = (g0 >= 0) ? *(const float2*)&g_cc[g0][c0] : make_float2(0.f, 0.f);
            cv1 = (g1 >= 0) ? *(const float2*)&g_cc[g1][c0] : make_float2(0.f, 0.f);
        }
        float v0 = fmaxf(acc1[j][0] + p0x * wx.x + p0y * wy.x + p0z * wz.x + cv0.x, 0.f);
        float v1 = fmaxf(acc1[j][1] + p0x * wx.y + p0y * wy.y + p0z * wz.y + cv0.y, 0.f);
        float v2 = fmaxf(acc1[j][2] + p1x * wx.x + p1y * wy.x + p1z * wz.x + cv1.x, 0.f);
        float v3 = fmaxf(acc1[j][3] + p1x * wx.y + p1y * wy.y + p1z * wz.y + cv1.y, 0.f);
        ahi[j][0] = pk_hi(v0, v1); ahi[j][1] = pk_hi(v2, v3);
        alo[j][0] = pk_lo(v0, v1); alo[j][1] = pk_lo(v2, v3);
    }

    // ---------- phase 2: acc2 = H @ W2 (3-term) ----------
    float acc2[16][4];
    #pragma unroll
    for (int j = 0; j < 16; j++)
        #pragma unroll
        for (int q = 0; q < 4; q++) acc2[j][q] = 0.f;

    #pragma unroll
    for (int t = 0; t < 8; t++) {
        uint32_t Ahi[4] = { ahi[2 * t][0], ahi[2 * t][1], ahi[2 * t + 1][0], ahi[2 * t + 1][1] };
        uint32_t Alo[4] = { alo[2 * t][0], alo[2 * t][1], alo[2 * t + 1][0], alo[2 * t + 1][1] };
        const uint4* wf = g_W2f + (t * 16) * 32 + l;
        #pragma unroll
        for (int j = 0; j < 16; j++) {
            uint4 B = wf[j * 32];
            mma16816(acc2[j], Ahi, B.x, B.y);
            mma16816(acc2[j], Ahi, B.z, B.w);
            mma16816(acc2[j], Alo, B.x, B.y);
        }
    }

    // ---------- epilogue 2: segment-max + atomic flush ----------
    if (uni) {
        #pragma unroll
        for (int j = 0; j < 16; j++) {
            float m0 = fmaxf(acc2[j][0], acc2[j][2]);
            float m1 = fmaxf(acc2[j][1], acc2[j][3]);
            #pragma unroll
            for (int d = 4; d < 32; d <<= 1) {
                m0 = fmaxf(m0, __shfl_xor_sync(0xffffffffu, m0, d));
                m1 = fmaxf(m1, __shfl_xor_sync(0xffffffffu, m1, d));
            }
            if (l < 4) {
                int c0 = 8 * j + m4;
                red[wid * 128 + c0] = m0;
                red[wid * 128 + c0 + 1] = m1;
            }
        }
        __syncthreads();
        if (tid < 128) {
            float m = red[tid];
            #pragma unroll
            for (int w = 1; w < 8; w++) m = fmaxf(m, red[w * 128 + tid]);
            atomicMaxFloat(&out[gu * DO + tid], m + b2s[tid]);
        }
    } else {
        #pragma unroll
        for (int j = 0; j < 16; j++) {
            int c0 = 8 * j + m4;
            if (g0 >= 0) {
                atomicMaxFloat(&out[g0 * DO + c0],     acc2[j][0] + b2s[c0]);
                atomicMaxFloat(&out[g0 * DO + c0 + 1], acc2[j][1] + b2s[c0 + 1]);
            }
            if (g1 >= 0) {
                atomicMaxFloat(&out[g1 * DO + c0],     acc2[j][2] + b2s[c0]);
                atomicMaxFloat(&out[g1 * DO + c0 + 1], acc2[j][3] + b2s[c0 + 1]);
            }
        }
    }
}

// ---------------- launch ----------------
extern "C" void kernel_launch(void* const* d_in, const int* in_sizes, int n_in,
                              void* d_out, int out_size) {
    const float* x     = (const float*)d_in[0];
    const float* pos   = (const float*)d_in[1];
    const int*   batch = (const int*)d_in[2];
    const float* lf    = (const float*)d_in[3];
    const float* W1    = (const float*)d_in[4];
    const float* b1    = (const float*)d_in[5];
    const float* W2    = (const float*)d_in[6];
    const float* b2    = (const float*)d_in[7];
    float* out = (float*)d_out;

    k_init<<<32, 256>>>(out, out_size);
    k_stats<<<64, 256>>>(pos, batch);
    k_argmin<<<64, 256>>>(pos, batch);
    k_center<<<BGR, DH>>>(x, pos, batch, lf, W1, b1, out, out_size);
    k_wprep<<<16, 256>>>(W1, W2);
    int grid = (NPTS + TILE - 1) / TILE;
    k_main<<<grid, 256>>>(x, pos, batch, W1, b2, out);
}

// round 4
// speedup vs baseline: 3.2157x; 1.1940x over previous
#include <cuda_runtime.h>
#include <cuda_bf16.h>
#include <math_constants.h>
#include <limits.h>
#include <stdint.h>

#define NPTS 500000
#define BGR 64
#define DIN 64
#define DH 128
#define DO 128
#define TILE 128

// ---------------- device scratch ----------------
__device__ float g_psum[BGR][3];
__device__ float g_cnt[BGR];
__device__ unsigned long long g_amin[BGR];
__device__ float g_cc[BGR][DH];
// weight fragments: [kchunk][ntile(16)][lane(32)] -> uint4 {bhi0,bhi1,blo0,blo1}
__device__ uint4 g_W1f[4 * 16 * 32];
__device__ uint4 g_W2f[8 * 16 * 32];

__device__ __forceinline__ void atomicMaxFloat(float* addr, float val) {
    if (val >= 0.0f) atomicMax((int*)addr, __float_as_int(val));
    else             atomicMin((unsigned int*)addr, __float_as_uint(val));
}

__device__ __forceinline__ uint32_t pk_hi(float a, float b) {
    __nv_bfloat162 t = __halves2bfloat162(__float2bfloat16_rn(a), __float2bfloat16_rn(b));
    return *(uint32_t*)&t;
}
__device__ __forceinline__ uint32_t pk_lo(float a, float b) {
    float ra = a - __bfloat162float(__float2bfloat16_rn(a));
    float rb = b - __bfloat162float(__float2bfloat16_rn(b));
    __nv_bfloat162 t = __halves2bfloat162(__float2bfloat16_rn(ra), __float2bfloat16_rn(rb));
    return *(uint32_t*)&t;
}

__device__ __forceinline__ void mma16816(float* c, const uint32_t* a, uint32_t b0, uint32_t b1) {
    asm volatile(
        "mma.sync.aligned.m16n8k16.row.col.f32.bf16.bf16.f32 "
        "{%0,%1,%2,%3}, {%4,%5,%6,%7}, {%8,%9}, {%0,%1,%2,%3};"
        : "+f"(c[0]), "+f"(c[1]), "+f"(c[2]), "+f"(c[3])
        : "r"(a[0]), "r"(a[1]), "r"(a[2]), "r"(a[3]), "r"(b0), "r"(b1));
}

// ---------------- small kernels ----------------
__global__ void k_init(float* out, int out_size) {
    int i = blockIdx.x * blockDim.x + threadIdx.x;
    if (blockIdx.x == 0) {
        if (threadIdx.x < BGR) { g_cnt[threadIdx.x] = 0.f; g_amin[threadIdx.x] = ~0ull; }
        if (threadIdx.x < BGR * 3) ((float*)g_psum)[threadIdx.x] = 0.f;
    }
    int lim = (BGR * DO < out_size) ? BGR * DO : out_size;
    for (int j = i; j < lim; j += gridDim.x * blockDim.x) out[j] = -CUDART_INF_F;
}

__global__ void k_stats(const float* __restrict__ pos, const int* __restrict__ batch) {
    const int T = gridDim.x * blockDim.x;
    int t = blockIdx.x * blockDim.x + threadIdx.x;
    int chunk = (NPTS + T - 1) / T;
    int s = t * chunk;
    int e = s + chunk; if (e > NPTS) e = NPTS;
    if (s >= e) return;
    int cg = batch[s];
    float sx = 0.f, sy = 0.f, sz = 0.f, c = 0.f;
    for (int i = s; i < e; i++) {
        int g = batch[i];
        if (g != cg) {
            atomicAdd(&g_psum[cg][0], sx); atomicAdd(&g_psum[cg][1], sy);
            atomicAdd(&g_psum[cg][2], sz); atomicAdd(&g_cnt[cg], c);
            cg = g; sx = sy = sz = 0.f; c = 0.f;
        }
        sx += pos[3 * i]; sy += pos[3 * i + 1]; sz += pos[3 * i + 2]; c += 1.f;
    }
    atomicAdd(&g_psum[cg][0], sx); atomicAdd(&g_psum[cg][1], sy);
    atomicAdd(&g_psum[cg][2], sz); atomicAdd(&g_cnt[cg], c);
}

__global__ void k_argmin(const float* __restrict__ pos, const int* __restrict__ batch) {
    const int T = gridDim.x * blockDim.x;
    int t = blockIdx.x * blockDim.x + threadIdx.x;
    int chunk = (NPTS + T - 1) / T;
    int s = t * chunk;
    int e = s + chunk; if (e > NPTS) e = NPTS;
    if (s >= e) return;
    int cg = -1;
    float cx = 0.f, cy = 0.f, cz = 0.f;
    unsigned long long best = ~0ull;
    for (int i = s; i < e; i++) {
        int g = batch[i];
        if (g != cg) {
            if (cg >= 0) atomicMin(&g_amin[cg], best);
            cg = g; best = ~0ull;
            float cnt = fmaxf(g_cnt[g], 1.0f);
            cx = g_psum[g][0] / cnt; cy = g_psum[g][1] / cnt; cz = g_psum[g][2] / cnt;
        }
        float dx = pos[3 * i] - cx, dy = pos[3 * i + 1] - cy, dz = pos[3 * i + 2] - cz;
        float d = sqrtf(dx * dx + dy * dy + dz * dz);
        unsigned long long key = ((unsigned long long)__float_as_uint(d) << 32) | (unsigned)i;
        if (key < best) best = key;
    }
    if (cg >= 0) atomicMin(&g_amin[cg], best);
}

__global__ void k_center(const float* __restrict__ x, const float* __restrict__ pos,
                         const int* __restrict__ batch, const float* __restrict__ lf,
                         const float* __restrict__ W1, const float* __restrict__ b1,
                         float* out, int out_size) {
    __shared__ float sx[DIN];
    __shared__ float sp[3];
    __shared__ int sidx;
    int g = blockIdx.x;
    int j = threadIdx.x;  // 0..127
    if (j == 0) {
        unsigned long long key = g_amin[g];
        sidx = (g_cnt[g] > 0.f) ? (int)(unsigned)(key & 0xffffffffu) : (NPTS - 1);
    }
    __syncthreads();
    int idx = sidx;
    if (j < DIN) sx[j] = x[(size_t)idx * DIN + j];
    if (j < 3) sp[j] = pos[3 * idx + j];
    __syncthreads();
    float c = b1[j];
    #pragma unroll 8
    for (int k = 0; k < DIN; k++)
        c += sx[k] * (W1[k * DH + j] - W1[(DIN + k) * DH + j]);
    c -= sp[0] * W1[(2 * DIN) * DH + j] + sp[1] * W1[(2 * DIN + 1) * DH + j]
       + sp[2] * W1[(2 * DIN + 2) * DH + j];
    g_cc[g][j] = c;
    if (j < 3)  { int o = BGR * DO + g * 3 + j;               if (o < out_size) out[o] = sp[j]; }
    if (j == 0) { int o = BGR * DO + BGR * 3 + g;             if (o < out_size) out[o] = (float)batch[idx]; }
    if (j < 9)  { int o = BGR * DO + BGR * 3 + BGR + g*9 + j; if (o < out_size) out[o] = lf[(size_t)idx * 9 + j]; }
}

// ---------------- weight prep: pack mma.sync B-fragments, hi/lo split ------
__global__ void k_wprep(const float* __restrict__ W1, const float* __restrict__ W2) {
    int i = blockIdx.x * blockDim.x + threadIdx.x;
    if (i < 4 * 16 * 32) {   // W1x fragment: t(4), j(16), l(32)
        int l = i & 31, t = i >> 9;
        int n = 8 * ((i >> 5) & 15) + (l >> 2);
        int k0 = 16 * t + 2 * (l & 3);
        float w00 = W1[(DIN + k0) * DH + n];
        float w01 = W1[(DIN + k0 + 1) * DH + n];
        float w10 = W1[(DIN + k0 + 8) * DH + n];
        float w11 = W1[(DIN + k0 + 9) * DH + n];
        uint4 v;
        v.x = pk_hi(w00, w01); v.y = pk_hi(w10, w11);
        v.z = pk_lo(w00, w01); v.w = pk_lo(w10, w11);
        g_W1f[i] = v;
    }
    if (i < 8 * 16 * 32) {   // W2 fragment: t(8), j(16), l(32)
        int l = i & 31, t = i >> 9;
        int n = 8 * ((i >> 5) & 15) + (l >> 2);
        int k0 = 16 * t + 2 * (l & 3);
        float w00 = W2[k0 * DO + n];
        float w01 = W2[(k0 + 1) * DO + n];
        float w10 = W2[(k0 + 8) * DO + n];
        float w11 = W2[(k0 + 9) * DO + n];
        uint4 v;
        v.x = pk_hi(w00, w01); v.y = pk_hi(w10, w11);
        v.z = pk_lo(w00, w01); v.w = pk_lo(w10, w11);
        g_W2f[i] = v;
    }
}

// ---------------- main fused mma.sync kernel (2 CTAs/SM) ----------------
__global__ void __launch_bounds__(256, 2) k_main(
    const float* __restrict__ x, const float* __restrict__ pos,
    const int* __restrict__ batch, const float* __restrict__ W1,
    const float* __restrict__ b2, float* __restrict__ out) {

    __shared__ float wpx[128], wpy[128], wpz[128];
    __shared__ float cgs[128], b2s[128];
    __shared__ float px[128], py[128], pz[128];
    __shared__ float red[8 * 128];
    __shared__ int gbs[128];

    const int tid = threadIdx.x;
    const int wid = tid >> 5, l = tid & 31;
    const int row0 = blockIdx.x * TILE;

    // setup
    if (tid < 128) {
        wpx[tid] = W1[(2 * DIN + 0) * DH + tid];
        wpy[tid] = W1[(2 * DIN + 1) * DH + tid];
        wpz[tid] = W1[(2 * DIN + 2) * DH + tid];
        b2s[tid] = b2[tid];
        int row = row0 + tid;
        if (row < NPTS) {
            px[tid] = pos[3 * row]; py[tid] = pos[3 * row + 1]; pz[tid] = pos[3 * row + 2];
            gbs[tid] = batch[row];
        } else {
            px[tid] = py[tid] = pz[tid] = 0.f;
            gbs[tid] = -1;
        }
    }
    __syncthreads();
    const int gu = gbs[0];
    const bool uni = (gu >= 0) && (gu == gbs[127]);
    if (tid < 128) cgs[tid] = (gu >= 0) ? g_cc[gu][tid] : 0.f;
    __syncthreads();

    const int rr0 = wid * 16 + (l >> 2);
    const int rr1 = rr0 + 8;
    const int r0 = row0 + rr0, r1 = row0 + rr1;
    const int m4 = 2 * (l & 3);

    // ---------- load x fragments once (kept resident) ----------
    uint32_t xhi[4][4], xlo[4][4];
    #pragma unroll
    for (int t = 0; t < 4; t++) {
        const int kb = 16 * t + m4;
        float2 x00 = make_float2(0.f, 0.f), x01 = x00, x10 = x00, x11 = x00;
        if (r0 < NPTS) {
            x00 = *(const float2*)(x + (size_t)r0 * DIN + kb);
            x01 = *(const float2*)(x + (size_t)r0 * DIN + kb + 8);
        }
        if (r1 < NPTS) {
            x10 = *(const float2*)(x + (size_t)r1 * DIN + kb);
            x11 = *(const float2*)(x + (size_t)r1 * DIN + kb + 8);
        }
        xhi[t][0] = pk_hi(x00.x, x00.y); xhi[t][1] = pk_hi(x10.x, x10.y);
        xhi[t][2] = pk_hi(x01.x, x01.y); xhi[t][3] = pk_hi(x11.x, x11.y);
        xlo[t][0] = pk_lo(x00.x, x00.y); xlo[t][1] = pk_lo(x10.x, x10.y);
        xlo[t][2] = pk_lo(x01.x, x01.y); xlo[t][3] = pk_lo(x11.x, x11.y);
    }

    const float p0x = px[rr0], p0y = py[rr0], p0z = pz[rr0];
    const float p1x = px[rr1], p1y = py[rr1], p1z = pz[rr1];
    const int g0 = gbs[rr0], g1 = gbs[rr1];

    // ---------- phase 1 in two 64-col halves -> H fragments ----------
    uint32_t ahi[16][2], alo[16][2];
    #pragma unroll
    for (int h = 0; h < 2; h++) {
        float acc1[8][4];
        #pragma unroll
        for (int j = 0; j < 8; j++)
            #pragma unroll
            for (int q = 0; q < 4; q++) acc1[j][q] = 0.f;

        #pragma unroll
        for (int t = 0; t < 4; t++) {
            const uint4* wf = g_W1f + (t * 16 + h * 8) * 32 + l;
            #pragma unroll
            for (int j = 0; j < 8; j++) {
                uint4 B = wf[j * 32];
                mma16816(acc1[j], xhi[t], B.x, B.y);   // hh
                mma16816(acc1[j], xhi[t], B.z, B.w);   // hi * lo
                mma16816(acc1[j], xlo[t], B.x, B.y);   // lo * hi
            }
        }

        // epilogue 1 for this half: + pos*Wp + c_g, relu, split -> A-frags
        #pragma unroll
        for (int j = 0; j < 8; j++) {
            int jj = h * 8 + j;
            int c0 = 8 * jj + m4;
            float2 wx = *(float2*)&wpx[c0];
            float2 wy = *(float2*)&wpy[c0];
            float2 wz = *(float2*)&wpz[c0];
            float2 cv0, cv1;
            if (uni) {
                cv0 = *(float2*)&cgs[c0]; cv1 = cv0;
            } else {
                cv0 = (g0 >= 0) ? *(const float2*)&g_cc[g0][c0] : make_float2(0.f, 0.f);
                cv1 = (g1 >= 0) ? *(const float2*)&g_cc[g1][c0] : make_float2(0.f, 0.f);
            }
            float v0 = fmaxf(acc1[j][0] + p0x * wx.x + p0y * wy.x + p0z * wz.x + cv0.x, 0.f);
            float v1 = fmaxf(acc1[j][1] + p0x * wx.y + p0y * wy.y + p0z * wz.y + cv0.y, 0.f);
            float v2 = fmaxf(acc1[j][2] + p1x * wx.x + p1y * wy.x + p1z * wz.x + cv1.x, 0.f);
            float v3 = fmaxf(acc1[j][3] + p1x * wx.y + p1y * wy.y + p1z * wz.y + cv1.y, 0.f);
            ahi[jj][0] = pk_hi(v0, v1); ahi[jj][1] = pk_hi(v2, v3);
            alo[jj][0] = pk_lo(v0, v1); alo[jj][1] = pk_lo(v2, v3);
        }
    }

    // ---------- phase 2 in two 64-col halves ----------
    #pragma unroll
    for (int h = 0; h < 2; h++) {
        float acc2[8][4];
        #pragma unroll
        for (int j = 0; j < 8; j++)
            #pragma unroll
            for (int q = 0; q < 4; q++) acc2[j][q] = 0.f;

        #pragma unroll
        for (int t = 0; t < 8; t++) {
            uint32_t Ahi[4] = { ahi[2 * t][0], ahi[2 * t][1], ahi[2 * t + 1][0], ahi[2 * t + 1][1] };
            uint32_t Alo[4] = { alo[2 * t][0], alo[2 * t][1], alo[2 * t + 1][0], alo[2 * t + 1][1] };
            const uint4* wf = g_W2f + (t * 16 + h * 8) * 32 + l;
            #pragma unroll
            for (int j = 0; j < 8; j++) {
                uint4 B = wf[j * 32];
                mma16816(acc2[j], Ahi, B.x, B.y);
                mma16816(acc2[j], Ahi, B.z, B.w);
                mma16816(acc2[j], Alo, B.x, B.y);
            }
        }

        // epilogue 2 for this half
        if (uni) {
            #pragma unroll
            for (int j = 0; j < 8; j++) {
                int c0 = 8 * (h * 8 + j) + m4;
                float m0 = fmaxf(acc2[j][0], acc2[j][2]);
                float m1 = fmaxf(acc2[j][1], acc2[j][3]);
                #pragma unroll
                for (int d = 4; d < 32; d <<= 1) {
                    m0 = fmaxf(m0, __shfl_xor_sync(0xffffffffu, m0, d));
                    m1 = fmaxf(m1, __shfl_xor_sync(0xffffffffu, m1, d));
                }
                if (l < 4) {
                    red[wid * 128 + c0] = m0;
                    red[wid * 128 + c0 + 1] = m1;
                }
            }
        } else {
            #pragma unroll
            for (int j = 0; j < 8; j++) {
                int c0 = 8 * (h * 8 + j) + m4;
                if (g0 >= 0) {
                    atomicMaxFloat(&out[g0 * DO + c0],     acc2[j][0] + b2s[c0]);
                    atomicMaxFloat(&out[g0 * DO + c0 + 1], acc2[j][1] + b2s[c0 + 1]);
                }
                if (g1 >= 0) {
                    atomicMaxFloat(&out[g1 * DO + c0],     acc2[j][2] + b2s[c0]);
                    atomicMaxFloat(&out[g1 * DO + c0 + 1], acc2[j][3] + b2s[c0 + 1]);
                }
            }
        }
    }

    if (uni) {
        __syncthreads();
        if (tid < 128) {
            float m = red[tid];
            #pragma unroll
            for (int w = 1; w < 8; w++) m = fmaxf(m, red[w * 128 + tid]);
            atomicMaxFloat(&out[gu * DO + tid], m + b2s[tid]);
        }
    }
}

// ---------------- launch ----------------
extern "C" void kernel_launch(void* const* d_in, const int* in_sizes, int n_in,
                              void* d_out, int out_size) {
    const float* x     = (const float*)d_in[0];
    const float* pos   = (const float*)d_in[1];
    const int*   batch = (const int*)d_in[2];
    const float* lf    = (const float*)d_in[3];
    const float* W1    = (const float*)d_in[4];
    const float* b1    = (const float*)d_in[5];
    const float* W2    = (const float*)d_in[6];
    const float* b2    = (const float*)d_in[7];
    float* out = (float*)d_out;

    k_init<<<32, 256>>>(out, out_size);
    k_stats<<<64, 256>>>(pos, batch);
    k_argmin<<<64, 256>>>(pos, batch);
    k_center<<<BGR, DH>>>(x, pos, batch, lf, W1, b1, out, out_size);
    k_wprep<<<16, 256>>>(W1, W2);
    int grid = (NPTS + TILE - 1) / TILE;
    k_main<<<grid, 256>>>(x, pos, batch, W1, b2, out);
}